// round 15
// baseline (speedup 1.0000x reference)
#include <cuda_runtime.h>
#include <cuda_bf16.h>
#include <math.h>
#include <stdint.h>

#define Nn 2048
#define Dd 4096
#define NC 21
#define NBB 84
#define NOUT 105

#define JAX_PARTITIONABLE 1

// ---------------- scratch (static device globals; no allocations) ----------
__device__ float g_X[(size_t)Nn * Dd];
__device__ float g_P0[(size_t)Nn * Dd];   // split-K partial 0
__device__ float g_P1[(size_t)Nn * Dd];   // split-K partial 1
__device__ __nv_bfloat16 gAh[(size_t)Nn * Dd];
__device__ __nv_bfloat16 gAl[(size_t)Nn * Dd];
__device__ __nv_bfloat16 gBh[(size_t)Dd * Dd];   // transposed: [N][K]
__device__ __nv_bfloat16 gBl[(size_t)Dd * Dd];
__device__ int   g_ctr[512];              // per-tile split-K arrival counters
__device__ float g_bx1[Nn], g_by1[Nn], g_bx2[Nn], g_by2[Nn];
__device__ float g_area[Nn], g_cx[Nn], g_cy[Nn];
__device__ int   g_cols[Nn * 5];
__device__ float g_vals[Nn * 5];
__device__ int   g_cnt[Nn];
__device__ unsigned g_keys[6];

// ---------------- threefry-2x32 (bit-exact vs jax) --------------------------
__device__ __forceinline__ unsigned rotl32_(unsigned x, int r) {
    return (x << r) | (x >> (32 - r));
}

__device__ __forceinline__ void tf2x32(unsigned k0, unsigned k1,
                                       unsigned x0, unsigned x1,
                                       unsigned& o0, unsigned& o1) {
    unsigned ks2 = k0 ^ k1 ^ 0x1BD11BDAu;
    x0 += k0; x1 += k1;
#define TFR(r) { x0 += x1; x1 = rotl32_(x1, r); x1 ^= x0; }
    TFR(13) TFR(15) TFR(26) TFR(6)
    x0 += k1; x1 += ks2 + 1u;
    TFR(17) TFR(29) TFR(16) TFR(24)
    x0 += ks2; x1 += k0 + 2u;
    TFR(13) TFR(15) TFR(26) TFR(6)
    x0 += k0; x1 += k1 + 3u;
    TFR(17) TFR(29) TFR(16) TFR(24)
    x0 += k1; x1 += ks2 + 4u;
    TFR(13) TFR(15) TFR(26) TFR(6)
    x0 += ks2; x1 += k0 + 5u;
#undef TFR
    o0 = x0; o1 = x1;
}

__device__ __forceinline__ float jax_uniform(unsigned k0, unsigned k1, unsigned m) {
    unsigned o0, o1, bits;
#if JAX_PARTITIONABLE
    tf2x32(k0, k1, 0u, m, o0, o1);
    bits = o0 ^ o1;
#else
    const unsigned half = (unsigned)(Nn) * (unsigned)(Nn) / 2u;
    if (m < half) { tf2x32(k0, k1, m, m + half, o0, o1); bits = o0; }
    else          { tf2x32(k0, k1, m - half, m, o0, o1); bits = o1; }
#endif
    return __uint_as_float((bits >> 9) | 0x3F800000u) - 1.0f;
}

// ---------------- box prep (+ PRNG keys folded in) ---------------------------
__global__ void k_boxprep(const float* __restrict__ rois) {
    int i = blockIdx.x * blockDim.x + threadIdx.x;
    if (i == 0) {
        unsigned o0, o1;
#if JAX_PARTITIONABLE
        for (unsigned t = 0; t < 3; t++) {
            tf2x32(0u, 42u, 0u, t, o0, o1);
            g_keys[2 * t] = o0; g_keys[2 * t + 1] = o1;
        }
#else
        tf2x32(0u, 42u, 0u, 3u, o0, o1); g_keys[0] = o0; g_keys[3] = o1;
        tf2x32(0u, 42u, 1u, 4u, o0, o1); g_keys[1] = o0; g_keys[4] = o1;
        tf2x32(0u, 42u, 2u, 5u, o0, o1); g_keys[2] = o0; g_keys[5] = o1;
#endif
    }
    if (i < Nn) {
        float x1 = rois[i * 5 + 1], y1 = rois[i * 5 + 2];
        float x2 = rois[i * 5 + 3], y2 = rois[i * 5 + 4];
        g_bx1[i] = x1; g_by1[i] = y1; g_bx2[i] = x2; g_by2[i] = y2;
        g_area[i] = (x2 - x1 + 1.0f) * (y2 - y1 + 1.0f);
        g_cx[i] = (x1 + x2) * 0.5f;
        g_cy[i] = (y1 + y2) * 0.5f;
    }
}

// ---------------- mask construction (one block per row) ---------------------
__global__ void k_mask() {
    int i = blockIdx.x;
    __shared__ float p1[Nn]; __shared__ int id1[Nn];
    __shared__ float p2[Nn]; __shared__ int id2[Nn];
    __shared__ int n1, n2;
    if (threadIdx.x == 0) { n1 = 0; n2 = 0; }
    __syncthreads();

    float xi1 = g_bx1[i], yi1 = g_by1[i], xi2 = g_bx2[i], yi2 = g_by2[i];
    float ai = g_area[i], cxi = g_cx[i], cyi = g_cy[i];
    unsigned K1a = g_keys[0], K1b = g_keys[1];
    unsigned K2a = g_keys[2], K2b = g_keys[3];

    for (int j = threadIdx.x; j < Nn; j += blockDim.x) {
        float iw = fminf(xi2, g_bx2[j]) - fmaxf(xi1, g_bx1[j]) + 1.0f;
        float ih = fminf(yi2, g_by2[j]) - fmaxf(yi1, g_by1[j]) + 1.0f;
        iw = fmaxf(iw, 0.0f); ih = fmaxf(ih, 0.0f);
        float inter = iw * ih;
        float iou = inter / (ai + g_area[j] - inter);
        if (iou >= 0.7f) {
            int p = atomicAdd(&n1, 1);
            p1[p] = jax_uniform(K1a, K1b, (unsigned)(i * Nn + j));
            id1[p] = j;
        }
        float dx = cxi - g_cx[j], dy = cyi - g_cy[j];
        float dist = sqrtf(dx * dx + dy * dy) / 1000.0f;
        if (dist < 0.01f) {
            int p = atomicAdd(&n2, 1);
            p2[p] = jax_uniform(K2a, K2b, (unsigned)(i * Nn + j));
            id2[p] = j;
        }
    }
    __syncthreads();

    if (threadIdx.x == 0) {
        int U[12]; float pu[12]; int nu = 0;
        int m1 = n1 < 6 ? n1 : 6;
        for (int k = 0; k < m1; k++) {
            int best = -1, bi = 0x7fffffff; float bp = -1.0f;
            for (int t = 0; t < n1; t++) {
                float v = p1[t];
                if (v < -1.0f) continue;
                if (v > bp || (v == bp && id1[t] < bi)) { best = t; bp = v; bi = id1[t]; }
            }
            p1[best] = -2.0f;
            U[nu++] = bi;
        }
        int m2 = n2 < 6 ? n2 : 6;
        for (int k = 0; k < m2; k++) {
            int best = -1, bi = 0x7fffffff; float bp = -1.0f;
            for (int t = 0; t < n2; t++) {
                float v = p2[t];
                if (v < -1.0f) continue;
                if (v > bp || (v == bp && id2[t] < bi)) { best = t; bp = v; bi = id2[t]; }
            }
            p2[best] = -2.0f;
            bool dup = false;
            for (int t = 0; t < nu; t++) if (U[t] == bi) { dup = true; break; }
            if (!dup) U[nu++] = bi;
        }
        unsigned K3a = g_keys[4], K3b = g_keys[5];
        for (int t = 0; t < nu; t++)
            pu[t] = jax_uniform(K3a, K3b, (unsigned)(i * Nn + U[t]));
        int F[4]; int nf = nu < 4 ? nu : 4;
        for (int k = 0; k < nf; k++) {
            int best = -1, bi = 0x7fffffff; float bp = -1.0f;
            for (int t = 0; t < nu; t++) {
                float v = pu[t];
                if (v < -1.0f) continue;
                if (v > bp || (v == bp && U[t] < bi)) { best = t; bp = v; bi = U[t]; }
            }
            pu[best] = -2.0f;
            F[k] = bi;
        }
        int cols[5]; int cnt = 0;
        cols[cnt++] = i;
        for (int k = 0; k < nf; k++) if (F[k] != i) cols[cnt++] = F[k];
        g_cnt[i] = cnt;
        for (int e = 0; e < cnt; e++) g_cols[i * 5 + e] = cols[e];
    }
}

// ------- sim values at the <=5 selected positions (norms fused in) ----------
__global__ void k_sim(const float* __restrict__ P) {
    int i = blockIdx.x;
    __shared__ float xs[Dd];
    __shared__ float red[8];
    __shared__ float s_sqi;
    int tid = threadIdx.x;
    const float4* Pi = (const float4*)(P + (size_t)i * Dd);
    float4* xs4 = (float4*)xs;
    float sq = 0.f;
    for (int q = tid; q < Dd / 4; q += blockDim.x) {
        float4 v = Pi[q];
        xs4[q] = v;
        sq += v.x * v.x + v.y * v.y + v.z * v.z + v.w * v.w;
    }
    for (int o = 16; o; o >>= 1) sq += __shfl_xor_sync(0xffffffffu, sq, o);
    if ((tid & 31) == 0) red[tid >> 5] = sq;
    __syncthreads();
    if (tid == 0) {
        float s = 0.f;
        for (int w = 0; w < 8; w++) s += red[w];
        s_sqi = s;
    }
    __syncthreads();

    int w = tid >> 5, lane = tid & 31;
    int cnt = g_cnt[i];
    if (w < cnt) {
        int j = g_cols[i * 5 + w];
        const float4* Pj = (const float4*)(P + (size_t)j * Dd);
        float acc = 0.f, sqj = 0.f;
        for (int q = lane; q < Dd / 4; q += 32) {
            float4 a = xs4[q], b = Pj[q];
            acc += a.x * b.x + a.y * b.y + a.z * b.z + a.w * b.w;
            sqj += b.x * b.x + b.y * b.y + b.z * b.z + b.w * b.w;
        }
        for (int o = 16; o; o >>= 1) {
            acc += __shfl_xor_sync(0xffffffffu, acc, o);
            sqj += __shfl_xor_sync(0xffffffffu, sqj, o);
        }
        if (lane == 0)
            g_vals[i * 5 + w] = acc / (sqrtf(s_sqi) * sqrtf(sqj));
    }
}

// ------- fused prep: sparse adj apply + bf16 hi/lo split (blocks < Nn),
//         W transpose+split (blocks Nn..); block Nn also zeroes g_ctr --------
__global__ void k_prep(const float* __restrict__ src, const float* __restrict__ W) {
    int tid = threadIdx.x;
    if (blockIdx.x < Nn) {
        int i = blockIdx.x;
        int cnt = g_cnt[i];
        int   cols[5]; float vals[5];
        for (int e = 0; e < cnt; e++) { cols[e] = g_cols[i * 5 + e]; vals[e] = g_vals[i * 5 + e]; }
        const float4* S4 = (const float4*)src;
        __nv_bfloat162* H2 = (__nv_bfloat162*)(gAh + (size_t)i * Dd);
        __nv_bfloat162* L2 = (__nv_bfloat162*)(gAl + (size_t)i * Dd);
        for (int q = tid; q < Dd / 4; q += blockDim.x) {
            float4 acc = make_float4(0.f, 0.f, 0.f, 0.f);
            for (int e = 0; e < cnt; e++) {
                float4 p = S4[(size_t)cols[e] * (Dd / 4) + q];
                float v = vals[e];
                acc.x += v * p.x; acc.y += v * p.y; acc.z += v * p.z; acc.w += v * p.w;
            }
            float vv[4] = {acc.x, acc.y, acc.z, acc.w};
            __nv_bfloat16 h[4], l[4];
#pragma unroll
            for (int t = 0; t < 4; t++) {
                h[t] = __float2bfloat16(vv[t]);
                l[t] = __float2bfloat16(vv[t] - __bfloat162float(h[t]));
            }
            H2[q * 2 + 0] = __nv_bfloat162(h[0], h[1]);
            H2[q * 2 + 1] = __nv_bfloat162(h[2], h[3]);
            L2[q * 2 + 0] = __nv_bfloat162(l[0], l[1]);
            L2[q * 2 + 1] = __nv_bfloat162(l[2], l[3]);
        }
    } else {
        if (blockIdx.x == Nn) {          // reset split-K counters for this layer
            g_ctr[tid] = 0;
            g_ctr[tid + 256] = 0;
        }
        __shared__ float ts[32][33];
        int bid = blockIdx.x - Nn;
        int n0 = (bid & 127) * 32, k0 = (bid >> 7) * 32;
        int tx = tid & 31, ty = tid >> 5;  // 32 x 8
#pragma unroll
        for (int q = 0; q < 4; q++) {
            int r = ty + q * 8;
            ts[r][tx] = W[(size_t)(k0 + r) * Dd + n0 + tx];
        }
        __syncthreads();
#pragma unroll
        for (int q = 0; q < 4; q++) {
            int n = ty + q * 8;
            float x = ts[tx][n];
            __nv_bfloat16 h = __float2bfloat16(x);
            __nv_bfloat16 l = __float2bfloat16(x - __bfloat162float(h));
            size_t o = (size_t)(n0 + n) * Dd + k0 + tx;
            gBh[o] = h;
            gBl[o] = l;
        }
    }
}

// ---------------- mma.sync + cp.async helpers -------------------------------
__device__ __forceinline__ uint32_t smem_u32(const void* p) {
    uint32_t a;
    asm("{ .reg .u64 t; cvta.to.shared.u64 t, %1; cvt.u32.u64 %0, t; }"
        : "=r"(a) : "l"(p));
    return a;
}

__device__ __forceinline__ void ldsm4(uint32_t* r, uint32_t addr) {
    asm volatile("ldmatrix.sync.aligned.m8n8.x4.shared.b16 {%0,%1,%2,%3}, [%4];"
                 : "=r"(r[0]), "=r"(r[1]), "=r"(r[2]), "=r"(r[3]) : "r"(addr));
}

__device__ __forceinline__ void mma16816(float* d, const uint32_t* a,
                                         const uint32_t* b) {
    asm volatile(
        "mma.sync.aligned.m16n8k16.row.col.f32.bf16.bf16.f32 "
        "{%0,%1,%2,%3}, {%4,%5,%6,%7}, {%8,%9}, {%0,%1,%2,%3};"
        : "+f"(d[0]), "+f"(d[1]), "+f"(d[2]), "+f"(d[3])
        : "r"(a[0]), "r"(a[1]), "r"(a[2]), "r"(a[3]), "r"(b[0]), "r"(b[1]));
}

__device__ __forceinline__ void cpa16(uint32_t dst, const void* src) {
    asm volatile("cp.async.cg.shared.global [%0], [%1], 16;"
                 :: "r"(dst), "l"(__cvta_generic_to_global(src)) : "memory");
}
__device__ __forceinline__ void cpcommit() {
    asm volatile("cp.async.commit_group;" ::: "memory");
}
__device__ __forceinline__ void cpwait1() {
    asm volatile("cp.async.wait_group 1;" ::: "memory");
}

// rows of 32 bf16 (64B); XOR-swizzle 16B column by row bits for ldmatrix
__device__ __forceinline__ uint32_t swz(uint32_t r, uint32_t x) {
    return r * 64u + (x ^ ((r & 6u) << 3));
}

// ---------------- split-bf16 tensor GEMM, split-K=2 -------------------------
// CTA tile 128(M) x 128(N), K-chunk 32, K-half 2048 per CTA (gridDim.z=2).
// Last CTA per tile combines partials + bias + relu into g_X (fused epilogue).
#define ST_AH 0
#define ST_AL 8192
#define ST_BH 16384
#define ST_BL 24576
#define STAGE_B 32768
#define GSMEM (3 * STAGE_B)

__global__ __launch_bounds__(256, 1)
void k_gemm_mma(const float* __restrict__ bias) {
    extern __shared__ __align__(16) char sm[];
    __shared__ int s_last;
    int tid = threadIdx.x, wid = tid >> 5, lane = tid & 31;
    int bx = blockIdx.x, by = blockIdx.y, bz = blockIdx.z;
    int warp_m = (wid >> 2) * 64;
    int warp_n = (wid & 3) * 32;
    uint32_t smb = smem_u32(sm);
    const int KBASE = bz * (Dd / 2);

    int cr = tid >> 2, cc = tid & 3;

    uint32_t aRO[4], aXR[4], bRO[2], bXR[2];
#pragma unroll
    for (int mt = 0; mt < 4; mt++) {
        uint32_t r = warp_m + mt * 16 + ((lane >> 3) & 1) * 8 + (lane & 7);
        aRO[mt] = r * 64u;
        aXR[mt] = (r & 6u) << 3;
    }
    uint32_t xa = (uint32_t)((lane >> 4) << 4);
#pragma unroll
    for (int p = 0; p < 2; p++) {
        uint32_t r = warp_n + p * 16 + ((lane >> 4) << 3) + (lane & 7);
        bRO[p] = r * 64u;
        bXR[p] = (r & 6u) << 3;
    }
    uint32_t xb = (uint32_t)(((lane >> 3) & 1) << 4);

    float acc[4][4][4];
#pragma unroll
    for (int mt = 0; mt < 4; mt++)
#pragma unroll
        for (int nt = 0; nt < 4; nt++)
#pragma unroll
            for (int q = 0; q < 4; q++) acc[mt][nt][q] = 0.f;

    const __nv_bfloat16* Ah0 = gAh + (size_t)(by * 128) * Dd + KBASE;
    const __nv_bfloat16* Al0 = gAl + (size_t)(by * 128) * Dd + KBASE;
    const __nv_bfloat16* Bh0 = gBh + (size_t)(bx * 128) * Dd + KBASE;
    const __nv_bfloat16* Bl0 = gBl + (size_t)(bx * 128) * Dd + KBASE;

#define ISSUE(stage, koff)                                                     \
    {                                                                          \
        uint32_t sb_ = smb + (stage) * STAGE_B;                                \
        _Pragma("unroll")                                                      \
        for (int q = 0; q < 2; q++) {                                          \
            uint32_t r = (uint32_t)(cr + q * 64);                              \
            uint32_t d = swz(r, (uint32_t)cc * 16);                            \
            cpa16(sb_ + ST_AH + d, Ah0 + (size_t)r * Dd + (koff) + cc * 8);    \
            cpa16(sb_ + ST_AL + d, Al0 + (size_t)r * Dd + (koff) + cc * 8);    \
            cpa16(sb_ + ST_BH + d, Bh0 + (size_t)r * Dd + (koff) + cc * 8);    \
            cpa16(sb_ + ST_BL + d, Bl0 + (size_t)r * Dd + (koff) + cc * 8);    \
        }                                                                      \
    }

    ISSUE(0, 0) cpcommit();
    ISSUE(1, 32) cpcommit();

    int sc = 0;   // compute stage
    int si = 2;   // issue stage
    const int NCH = (Dd / 2) / 32;  // 64
    for (int c = 0; c < NCH; c++) {
        cpwait1();
        __syncthreads();
        if (c + 2 < NCH) ISSUE(si, (c + 2) * 32)
        cpcommit();

        uint32_t sb = smb + sc * STAGE_B;
#pragma unroll
        for (int ks = 0; ks < 2; ks++) {
            uint32_t ka = (uint32_t)(ks * 32);
            uint32_t aH[4][4], aL[4][4], bH[2][4], bL[2][4];
#pragma unroll
            for (int p = 0; p < 2; p++)
                ldsm4(bH[p], sb + ST_BH + bRO[p] + ((ka + xb) ^ bXR[p]));
#pragma unroll
            for (int mt = 0; mt < 4; mt++)
                ldsm4(aH[mt], sb + ST_AH + aRO[mt] + ((ka + xa) ^ aXR[mt]));
            // hh
#pragma unroll
            for (int mt = 0; mt < 4; mt++)
#pragma unroll
                for (int nt = 0; nt < 4; nt++)
                    mma16816(acc[mt][nt], aH[mt], &bH[nt >> 1][(nt & 1) << 1]);
#pragma unroll
            for (int mt = 0; mt < 4; mt++)
                ldsm4(aL[mt], sb + ST_AL + aRO[mt] + ((ka + xa) ^ aXR[mt]));
            // lh
#pragma unroll
            for (int mt = 0; mt < 4; mt++)
#pragma unroll
                for (int nt = 0; nt < 4; nt++)
                    mma16816(acc[mt][nt], aL[mt], &bH[nt >> 1][(nt & 1) << 1]);
#pragma unroll
            for (int p = 0; p < 2; p++)
                ldsm4(bL[p], sb + ST_BL + bRO[p] + ((ka + xb) ^ bXR[p]));
            // hl
#pragma unroll
            for (int mt = 0; mt < 4; mt++)
#pragma unroll
                for (int nt = 0; nt < 4; nt++)
                    mma16816(acc[mt][nt], aH[mt], &bL[nt >> 1][(nt & 1) << 1]);
        }

        sc++; if (sc == 3) sc = 0;
        si++; if (si == 3) si = 0;
    }

    // ---- fused split-K epilogue ----
    float* Pz = bz ? g_P1 : g_P0;
    const float* Po = bz ? g_P0 : g_P1;
    int erow = by * 128 + warp_m + (lane >> 2);
    int ecol = bx * 128 + warp_n + (lane & 3) * 2;
#pragma unroll
    for (int mt = 0; mt < 4; mt++) {
#pragma unroll
        for (int nt = 0; nt < 4; nt++) {
            int row = erow + mt * 16;
            int col = ecol + nt * 8;
            *(float2*)(Pz + (size_t)row * Dd + col) =
                make_float2(acc[mt][nt][0], acc[mt][nt][1]);
            *(float2*)(Pz + (size_t)(row + 8) * Dd + col) =
                make_float2(acc[mt][nt][2], acc[mt][nt][3]);
        }
    }
    __threadfence();
    __syncthreads();
    if (tid == 0) s_last = atomicAdd(&g_ctr[by * 32 + bx], 1);
    __syncthreads();
    if (s_last == 1) {
        __threadfence();   // acquire: peer partial visible
#pragma unroll
        for (int mt = 0; mt < 4; mt++) {
#pragma unroll
            for (int nt = 0; nt < 4; nt++) {
                int row = erow + mt * 16;
                int col = ecol + nt * 8;
                float2 p0 = *(const float2*)(Po + (size_t)row * Dd + col);
                float2 p1 = *(const float2*)(Po + (size_t)(row + 8) * Dd + col);
                float b0 = bias[col], b1 = bias[col + 1];
                float2 o0, o1;
                o0.x = fmaxf((acc[mt][nt][0] + p0.x) + b0, 0.f);
                o0.y = fmaxf((acc[mt][nt][1] + p0.y) + b1, 0.f);
                o1.x = fmaxf((acc[mt][nt][2] + p1.x) + b0, 0.f);
                o1.y = fmaxf((acc[mt][nt][3] + p1.y) + b1, 0.f);
                *(float2*)(g_X + (size_t)row * Dd + col) = o0;
                *(float2*)(g_X + (size_t)(row + 8) * Dd + col) = o1;
            }
        }
    }
}

// ---------------- heads: 16 rows / block, smem-tiled ------------------------
__global__ __launch_bounds__(256)
void k_heads2(const float* __restrict__ Wc, const float* __restrict__ bc,
              const float* __restrict__ Wb, const float* __restrict__ bb_,
              float* __restrict__ out) {
    __shared__ float Xs[16][64];
    __shared__ float Ws[64][106];
    __shared__ float ob[16][105];
    int r0 = blockIdx.x * 16, tid = threadIdx.x;
    float acc[7];
#pragma unroll
    for (int it = 0; it < 7; it++) acc[it] = 0.f;

    for (int kc = 0; kc < 64; kc++) {
        for (int q = tid; q < 16 * 64; q += 256) {
            int r = q >> 6, k = q & 63;
            Xs[r][k] = g_X[(size_t)(r0 + r) * Dd + kc * 64 + k];
        }
        for (int q = tid; q < 64 * 105; q += 256) {
            int k = q / 105, cc = q % 105;
            Ws[k][cc] = (cc < NC) ? Wc[(size_t)(kc * 64 + k) * NC + cc]
                                  : Wb[(size_t)(kc * 64 + k) * NBB + (cc - NC)];
        }
        __syncthreads();
#pragma unroll
        for (int it = 0; it < 7; it++) {
            int o = tid + it * 256;
            if (o < 16 * 105) {
                int r = o / 105, cc = o % 105;
                float a = acc[it];
#pragma unroll 8
                for (int k = 0; k < 64; k++) a += Xs[r][k] * Ws[k][cc];
                acc[it] = a;
            }
        }
        __syncthreads();
    }

#pragma unroll
    for (int it = 0; it < 7; it++) {
        int o = tid + it * 256;
        if (o < 16 * 105) {
            int r = o / 105, cc = o % 105;
            ob[r][cc] = acc[it] + ((cc < NC) ? bc[cc] : bb_[cc - NC]);
        }
    }
    __syncthreads();

    int w = tid >> 5, lane = tid & 31;
    for (int rr = w; rr < 16; rr += 8) {
        float v = (lane < NC) ? ob[rr][lane] : -3.4e38f;
        float m = v;
        for (int o = 16; o; o >>= 1) m = fmaxf(m, __shfl_xor_sync(0xffffffffu, m, o));
        float e = (lane < NC) ? expf(v - m) : 0.f;
        float s = e;
        for (int o = 16; o; o >>= 1) s += __shfl_xor_sync(0xffffffffu, s, o);
        if (lane < NC) out[(size_t)(r0 + rr) * NOUT + lane] = e / s;
    }
    for (int q = tid; q < 16 * NBB; q += 256) {
        int rr = q / NBB, cc = NC + q % NBB;
        out[(size_t)(r0 + rr) * NOUT + cc] = ob[rr][cc];
    }
}

// ---------------- host orchestration ----------------------------------------
extern "C" void kernel_launch(void* const* d_in, const int* in_sizes, int n_in,
                              void* d_out, int out_size) {
    const float* rois = (const float*)d_in[0];
    const float* P    = (const float*)d_in[1];
    const float* W1   = (const float*)d_in[2];
    const float* b1   = (const float*)d_in[3];
    const float* W2   = (const float*)d_in[4];
    const float* b2   = (const float*)d_in[5];
    const float* Wc   = (const float*)d_in[6];
    const float* bc   = (const float*)d_in[7];
    const float* Wb   = (const float*)d_in[8];
    const float* bb   = (const float*)d_in[9];
    float* out = (float*)d_out;

    void* xaddr = nullptr;
    cudaGetSymbolAddress(&xaddr, g_X);

    cudaFuncSetAttribute(k_gemm_mma, cudaFuncAttributeMaxDynamicSharedMemorySize,
                         GSMEM);

    k_boxprep<<<(Nn + 255) / 256, 256>>>(rois);
    k_mask<<<Nn, 256>>>();
    k_sim<<<Nn, 256>>>(P);

    dim3 ggrid(Dd / 128, Nn / 128, 2);       // (32, 16, 2) split-K
    const int PREP_GRID = Nn + (Dd / 32) * (Dd / 32);  // 2048 + 16384

    // layer 1 (split-K combine + bias + relu fused into GEMM epilogue)
    k_prep<<<PREP_GRID, 256>>>(P, W1);
    k_gemm_mma<<<ggrid, 256, GSMEM>>>(b1);

    // layer 2
    k_prep<<<PREP_GRID, 256>>>((const float*)xaddr, W2);
    k_gemm_mma<<<ggrid, 256, GSMEM>>>(b2);

    k_heads2<<<Nn / 16, 256>>>(Wc, bc, Wb, bb, out);
}

// round 16
// speedup vs baseline: 1.2306x; 1.2306x over previous
#include <cuda_runtime.h>
#include <cuda_bf16.h>
#include <math.h>
#include <stdint.h>

#define Nn 2048
#define Dd 4096
#define NC 21
#define NBB 84
#define NOUT 105

#define JAX_PARTITIONABLE 1

// ---------------- scratch (static device globals; no allocations) ----------
__device__ float g_X[(size_t)Nn * Dd];
__device__ float g_P0[(size_t)Nn * Dd];   // split-K partial 0
__device__ float g_P1[(size_t)Nn * Dd];   // split-K partial 1
__device__ __nv_bfloat16 gAh[(size_t)Nn * Dd];
__device__ __nv_bfloat16 gAl[(size_t)Nn * Dd];
__device__ __nv_bfloat16 gBh[(size_t)Dd * Dd];   // transposed: [N][K]
__device__ __nv_bfloat16 gBl[(size_t)Dd * Dd];
__device__ float g_bx1[Nn], g_by1[Nn], g_bx2[Nn], g_by2[Nn];
__device__ float g_area[Nn], g_cx[Nn], g_cy[Nn];
__device__ int   g_cols[Nn * 5];
__device__ float g_vals[Nn * 5];
__device__ int   g_cnt[Nn];
__device__ unsigned g_keys[6];

// ---------------- threefry-2x32 (bit-exact vs jax) --------------------------
__device__ __forceinline__ unsigned rotl32_(unsigned x, int r) {
    return (x << r) | (x >> (32 - r));
}

__device__ __forceinline__ void tf2x32(unsigned k0, unsigned k1,
                                       unsigned x0, unsigned x1,
                                       unsigned& o0, unsigned& o1) {
    unsigned ks2 = k0 ^ k1 ^ 0x1BD11BDAu;
    x0 += k0; x1 += k1;
#define TFR(r) { x0 += x1; x1 = rotl32_(x1, r); x1 ^= x0; }
    TFR(13) TFR(15) TFR(26) TFR(6)
    x0 += k1; x1 += ks2 + 1u;
    TFR(17) TFR(29) TFR(16) TFR(24)
    x0 += ks2; x1 += k0 + 2u;
    TFR(13) TFR(15) TFR(26) TFR(6)
    x0 += k0; x1 += k1 + 3u;
    TFR(17) TFR(29) TFR(16) TFR(24)
    x0 += k1; x1 += ks2 + 4u;
    TFR(13) TFR(15) TFR(26) TFR(6)
    x0 += ks2; x1 += k0 + 5u;
#undef TFR
    o0 = x0; o1 = x1;
}

__device__ __forceinline__ float jax_uniform(unsigned k0, unsigned k1, unsigned m) {
    unsigned o0, o1, bits;
#if JAX_PARTITIONABLE
    tf2x32(k0, k1, 0u, m, o0, o1);
    bits = o0 ^ o1;
#else
    const unsigned half = (unsigned)(Nn) * (unsigned)(Nn) / 2u;
    if (m < half) { tf2x32(k0, k1, m, m + half, o0, o1); bits = o0; }
    else          { tf2x32(k0, k1, m - half, m, o0, o1); bits = o1; }
#endif
    return __uint_as_float((bits >> 9) | 0x3F800000u) - 1.0f;
}

__global__ void k_keys() {
    unsigned o0, o1;
#if JAX_PARTITIONABLE
    for (unsigned i = 0; i < 3; i++) {
        tf2x32(0u, 42u, 0u, i, o0, o1);
        g_keys[2 * i] = o0; g_keys[2 * i + 1] = o1;
    }
#else
    tf2x32(0u, 42u, 0u, 3u, o0, o1); g_keys[0] = o0; g_keys[3] = o1;
    tf2x32(0u, 42u, 1u, 4u, o0, o1); g_keys[1] = o0; g_keys[4] = o1;
    tf2x32(0u, 42u, 2u, 5u, o0, o1); g_keys[2] = o0; g_keys[5] = o1;
#endif
}

// ---------------- box prep --------------------------------------------------
__global__ void k_boxprep(const float* __restrict__ rois) {
    int i = blockIdx.x * blockDim.x + threadIdx.x;
    if (i < Nn) {
        float x1 = rois[i * 5 + 1], y1 = rois[i * 5 + 2];
        float x2 = rois[i * 5 + 3], y2 = rois[i * 5 + 4];
        g_bx1[i] = x1; g_by1[i] = y1; g_bx2[i] = x2; g_by2[i] = y2;
        g_area[i] = (x2 - x1 + 1.0f) * (y2 - y1 + 1.0f);
        g_cx[i] = (x1 + x2) * 0.5f;
        g_cy[i] = (y1 + y2) * 0.5f;
    }
}

// ---------------- mask construction (one block per row) ---------------------
__global__ void k_mask() {
    int i = blockIdx.x;
    __shared__ float p1[Nn]; __shared__ int id1[Nn];
    __shared__ float p2[Nn]; __shared__ int id2[Nn];
    __shared__ int n1, n2;
    if (threadIdx.x == 0) { n1 = 0; n2 = 0; }
    __syncthreads();

    float xi1 = g_bx1[i], yi1 = g_by1[i], xi2 = g_bx2[i], yi2 = g_by2[i];
    float ai = g_area[i], cxi = g_cx[i], cyi = g_cy[i];
    unsigned K1a = g_keys[0], K1b = g_keys[1];
    unsigned K2a = g_keys[2], K2b = g_keys[3];

    for (int j = threadIdx.x; j < Nn; j += blockDim.x) {
        float iw = fminf(xi2, g_bx2[j]) - fmaxf(xi1, g_bx1[j]) + 1.0f;
        float ih = fminf(yi2, g_by2[j]) - fmaxf(yi1, g_by1[j]) + 1.0f;
        iw = fmaxf(iw, 0.0f); ih = fmaxf(ih, 0.0f);
        float inter = iw * ih;
        float iou = inter / (ai + g_area[j] - inter);
        if (iou >= 0.7f) {
            int p = atomicAdd(&n1, 1);
            p1[p] = jax_uniform(K1a, K1b, (unsigned)(i * Nn + j));
            id1[p] = j;
        }
        float dx = cxi - g_cx[j], dy = cyi - g_cy[j];
        float dist = sqrtf(dx * dx + dy * dy) / 1000.0f;
        if (dist < 0.01f) {
            int p = atomicAdd(&n2, 1);
            p2[p] = jax_uniform(K2a, K2b, (unsigned)(i * Nn + j));
            id2[p] = j;
        }
    }
    __syncthreads();

    if (threadIdx.x == 0) {
        int U[12]; float pu[12]; int nu = 0;
        int m1 = n1 < 6 ? n1 : 6;
        for (int k = 0; k < m1; k++) {
            int best = -1, bi = 0x7fffffff; float bp = -1.0f;
            for (int t = 0; t < n1; t++) {
                float v = p1[t];
                if (v < -1.0f) continue;
                if (v > bp || (v == bp && id1[t] < bi)) { best = t; bp = v; bi = id1[t]; }
            }
            p1[best] = -2.0f;
            U[nu++] = bi;
        }
        int m2 = n2 < 6 ? n2 : 6;
        for (int k = 0; k < m2; k++) {
            int best = -1, bi = 0x7fffffff; float bp = -1.0f;
            for (int t = 0; t < n2; t++) {
                float v = p2[t];
                if (v < -1.0f) continue;
                if (v > bp || (v == bp && id2[t] < bi)) { best = t; bp = v; bi = id2[t]; }
            }
            p2[best] = -2.0f;
            bool dup = false;
            for (int t = 0; t < nu; t++) if (U[t] == bi) { dup = true; break; }
            if (!dup) U[nu++] = bi;
        }
        unsigned K3a = g_keys[4], K3b = g_keys[5];
        for (int t = 0; t < nu; t++)
            pu[t] = jax_uniform(K3a, K3b, (unsigned)(i * Nn + U[t]));
        int F[4]; int nf = nu < 4 ? nu : 4;
        for (int k = 0; k < nf; k++) {
            int best = -1, bi = 0x7fffffff; float bp = -1.0f;
            for (int t = 0; t < nu; t++) {
                float v = pu[t];
                if (v < -1.0f) continue;
                if (v > bp || (v == bp && U[t] < bi)) { best = t; bp = v; bi = U[t]; }
            }
            pu[best] = -2.0f;
            F[k] = bi;
        }
        int cols[5]; int cnt = 0;
        cols[cnt++] = i;
        for (int k = 0; k < nf; k++) if (F[k] != i) cols[cnt++] = F[k];
        g_cnt[i] = cnt;
        for (int e = 0; e < cnt; e++) g_cols[i * 5 + e] = cols[e];
    }
}

// ------- sim values at the <=5 selected positions (norms fused in) ----------
__global__ void k_sim(const float* __restrict__ P) {
    int i = blockIdx.x;
    __shared__ float xs[Dd];
    __shared__ float red[8];
    __shared__ float s_sqi;
    int tid = threadIdx.x;
    const float4* Pi = (const float4*)(P + (size_t)i * Dd);
    float4* xs4 = (float4*)xs;
    float sq = 0.f;
    for (int q = tid; q < Dd / 4; q += blockDim.x) {
        float4 v = Pi[q];
        xs4[q] = v;
        sq += v.x * v.x + v.y * v.y + v.z * v.z + v.w * v.w;
    }
    for (int o = 16; o; o >>= 1) sq += __shfl_xor_sync(0xffffffffu, sq, o);
    if ((tid & 31) == 0) red[tid >> 5] = sq;
    __syncthreads();
    if (tid == 0) {
        float s = 0.f;
        for (int w = 0; w < 8; w++) s += red[w];
        s_sqi = s;
    }
    __syncthreads();

    int w = tid >> 5, lane = tid & 31;
    int cnt = g_cnt[i];
    if (w < cnt) {
        int j = g_cols[i * 5 + w];
        const float4* Pj = (const float4*)(P + (size_t)j * Dd);
        float acc = 0.f, sqj = 0.f;
        for (int q = lane; q < Dd / 4; q += 32) {
            float4 a = xs4[q], b = Pj[q];
            acc += a.x * b.x + a.y * b.y + a.z * b.z + a.w * b.w;
            sqj += b.x * b.x + b.y * b.y + b.z * b.z + b.w * b.w;
        }
        for (int o = 16; o; o >>= 1) {
            acc += __shfl_xor_sync(0xffffffffu, acc, o);
            sqj += __shfl_xor_sync(0xffffffffu, sqj, o);
        }
        if (lane == 0)
            g_vals[i * 5 + w] = acc / (sqrtf(s_sqi) * sqrtf(sqj));
    }
}

// ------- fused prep: sparse adj apply + bf16 hi/lo split (blocks < Nn),
//         W transpose+split with wide stores (blocks Nn..) ------------------
// W-path: tile 32 n-cols x 64 k-rows; stores __nv_bfloat162 (128B/warp-row).
__global__ void k_prep(const float* __restrict__ src, const float* __restrict__ W) {
    int tid = threadIdx.x;
    if (blockIdx.x < Nn) {
        int i = blockIdx.x;
        int cnt = g_cnt[i];
        int   cols[5]; float vals[5];
        for (int e = 0; e < cnt; e++) { cols[e] = g_cols[i * 5 + e]; vals[e] = g_vals[i * 5 + e]; }
        const float4* S4 = (const float4*)src;
        __nv_bfloat162* H2 = (__nv_bfloat162*)(gAh + (size_t)i * Dd);
        __nv_bfloat162* L2 = (__nv_bfloat162*)(gAl + (size_t)i * Dd);
        for (int q = tid; q < Dd / 4; q += blockDim.x) {
            float4 acc = make_float4(0.f, 0.f, 0.f, 0.f);
            for (int e = 0; e < cnt; e++) {
                float4 p = S4[(size_t)cols[e] * (Dd / 4) + q];
                float v = vals[e];
                acc.x += v * p.x; acc.y += v * p.y; acc.z += v * p.z; acc.w += v * p.w;
            }
            float vv[4] = {acc.x, acc.y, acc.z, acc.w};
            __nv_bfloat16 h[4], l[4];
#pragma unroll
            for (int t = 0; t < 4; t++) {
                h[t] = __float2bfloat16(vv[t]);
                l[t] = __float2bfloat16(vv[t] - __bfloat162float(h[t]));
            }
            H2[q * 2 + 0] = __nv_bfloat162(h[0], h[1]);
            H2[q * 2 + 1] = __nv_bfloat162(h[2], h[3]);
            L2[q * 2 + 0] = __nv_bfloat162(l[0], l[1]);
            L2[q * 2 + 1] = __nv_bfloat162(l[2], l[3]);
        }
    } else {
        // tile: n0..n0+31 (W cols), k0..k0+63 (W rows)
        __shared__ float ts[64][33];
        int bid = blockIdx.x - Nn;
        int n0 = (bid & 127) * 32, k0 = (bid >> 7) * 64;
        int tx = tid & 31, ty = tid >> 5;  // 32 x 8
#pragma unroll
        for (int q = 0; q < 8; q++) {
            int r = ty + q * 8;  // k within tile (0..63)
            ts[r][tx] = W[(size_t)(k0 + r) * Dd + n0 + tx];
        }
        __syncthreads();
        // store: 32 n x 32 bf16x2 (=64 k) per tile; 4 iterations of 256 thr
#pragma unroll
        for (int q = 0; q < 4; q++) {
            int n = ty + q * 8;      // n within tile (0..31)
            float x0 = ts[2 * tx][n];
            float x1 = ts[2 * tx + 1][n];
            __nv_bfloat16 h0 = __float2bfloat16(x0);
            __nv_bfloat16 l0 = __float2bfloat16(x0 - __bfloat162float(h0));
            __nv_bfloat16 h1 = __float2bfloat16(x1);
            __nv_bfloat16 l1 = __float2bfloat16(x1 - __bfloat162float(h1));
            size_t o = ((size_t)(n0 + n) * Dd + k0) / 2 + tx;
            ((__nv_bfloat162*)gBh)[o] = __nv_bfloat162(h0, h1);
            ((__nv_bfloat162*)gBl)[o] = __nv_bfloat162(l0, l1);
        }
    }
}

// ---------------- mma.sync + cp.async helpers -------------------------------
__device__ __forceinline__ uint32_t smem_u32(const void* p) {
    uint32_t a;
    asm("{ .reg .u64 t; cvta.to.shared.u64 t, %1; cvt.u32.u64 %0, t; }"
        : "=r"(a) : "l"(p));
    return a;
}

__device__ __forceinline__ void ldsm4(uint32_t* r, uint32_t addr) {
    asm volatile("ldmatrix.sync.aligned.m8n8.x4.shared.b16 {%0,%1,%2,%3}, [%4];"
                 : "=r"(r[0]), "=r"(r[1]), "=r"(r[2]), "=r"(r[3]) : "r"(addr));
}

__device__ __forceinline__ void mma16816(float* d, const uint32_t* a,
                                         const uint32_t* b) {
    asm volatile(
        "mma.sync.aligned.m16n8k16.row.col.f32.bf16.bf16.f32 "
        "{%0,%1,%2,%3}, {%4,%5,%6,%7}, {%8,%9}, {%0,%1,%2,%3};"
        : "+f"(d[0]), "+f"(d[1]), "+f"(d[2]), "+f"(d[3])
        : "r"(a[0]), "r"(a[1]), "r"(a[2]), "r"(a[3]), "r"(b[0]), "r"(b[1]));
}

__device__ __forceinline__ void cpa16(uint32_t dst, const void* src) {
    asm volatile("cp.async.cg.shared.global [%0], [%1], 16;"
                 :: "r"(dst), "l"(__cvta_generic_to_global(src)) : "memory");
}
__device__ __forceinline__ void cpcommit() {
    asm volatile("cp.async.commit_group;" ::: "memory");
}
__device__ __forceinline__ void cpwait1() {
    asm volatile("cp.async.wait_group 1;" ::: "memory");
}

// rows of 32 bf16 (64B); XOR-swizzle 16B column by row bits for ldmatrix
__device__ __forceinline__ uint32_t swz(uint32_t r, uint32_t x) {
    return r * 64u + (x ^ ((r & 6u) << 3));
}

// ---------------- split-bf16 tensor GEMM, split-K=2 -------------------------
// CTA tile 128(M) x 128(N), K-chunk 32, K-half 2048 per CTA (gridDim.z=2).
// Raw fp32 partials to g_P0/g_P1; bias+relu fused in k_relu.
#define ST_AH 0
#define ST_AL 8192
#define ST_BH 16384
#define ST_BL 24576
#define STAGE_B 32768
#define GSMEM (3 * STAGE_B)

__global__ __launch_bounds__(256, 1)
void k_gemm_mma() {
    extern __shared__ __align__(16) char sm[];
    int tid = threadIdx.x, wid = tid >> 5, lane = tid & 31;
    int bx = blockIdx.x, by = blockIdx.y, bz = blockIdx.z;
    int warp_m = (wid >> 2) * 64;
    int warp_n = (wid & 3) * 32;
    uint32_t smb = smem_u32(sm);
    const int KBASE = bz * (Dd / 2);

    int cr = tid >> 2, cc = tid & 3;

    uint32_t aRO[4], aXR[4], bRO[2], bXR[2];
#pragma unroll
    for (int mt = 0; mt < 4; mt++) {
        uint32_t r = warp_m + mt * 16 + ((lane >> 3) & 1) * 8 + (lane & 7);
        aRO[mt] = r * 64u;
        aXR[mt] = (r & 6u) << 3;
    }
    uint32_t xa = (uint32_t)((lane >> 4) << 4);
#pragma unroll
    for (int p = 0; p < 2; p++) {
        uint32_t r = warp_n + p * 16 + ((lane >> 4) << 3) + (lane & 7);
        bRO[p] = r * 64u;
        bXR[p] = (r & 6u) << 3;
    }
    uint32_t xb = (uint32_t)(((lane >> 3) & 1) << 4);

    float acc[4][4][4];
#pragma unroll
    for (int mt = 0; mt < 4; mt++)
#pragma unroll
        for (int nt = 0; nt < 4; nt++)
#pragma unroll
            for (int q = 0; q < 4; q++) acc[mt][nt][q] = 0.f;

    const __nv_bfloat16* Ah0 = gAh + (size_t)(by * 128) * Dd + KBASE;
    const __nv_bfloat16* Al0 = gAl + (size_t)(by * 128) * Dd + KBASE;
    const __nv_bfloat16* Bh0 = gBh + (size_t)(bx * 128) * Dd + KBASE;
    const __nv_bfloat16* Bl0 = gBl + (size_t)(bx * 128) * Dd + KBASE;

#define ISSUE(stage, koff)                                                     \
    {                                                                          \
        uint32_t sb_ = smb + (stage) * STAGE_B;                                \
        _Pragma("unroll")                                                      \
        for (int q = 0; q < 2; q++) {                                          \
            uint32_t r = (uint32_t)(cr + q * 64);                              \
            uint32_t d = swz(r, (uint32_t)cc * 16);                            \
            cpa16(sb_ + ST_AH + d, Ah0 + (size_t)r * Dd + (koff) + cc * 8);    \
            cpa16(sb_ + ST_AL + d, Al0 + (size_t)r * Dd + (koff) + cc * 8);    \
            cpa16(sb_ + ST_BH + d, Bh0 + (size_t)r * Dd + (koff) + cc * 8);    \
            cpa16(sb_ + ST_BL + d, Bl0 + (size_t)r * Dd + (koff) + cc * 8);    \
        }                                                                      \
    }

    ISSUE(0, 0) cpcommit();
    ISSUE(1, 32) cpcommit();

    int sc = 0;   // compute stage
    int si = 2;   // issue stage
    const int NCH = (Dd / 2) / 32;  // 64
    for (int c = 0; c < NCH; c++) {
        cpwait1();
        __syncthreads();
        if (c + 2 < NCH) ISSUE(si, (c + 2) * 32)
        cpcommit();

        uint32_t sb = smb + sc * STAGE_B;
#pragma unroll
        for (int ks = 0; ks < 2; ks++) {
            uint32_t ka = (uint32_t)(ks * 32);
            uint32_t aH[4][4], aL[4][4], bH[2][4], bL[2][4];
#pragma unroll
            for (int p = 0; p < 2; p++)
                ldsm4(bH[p], sb + ST_BH + bRO[p] + ((ka + xb) ^ bXR[p]));
#pragma unroll
            for (int mt = 0; mt < 4; mt++)
                ldsm4(aH[mt], sb + ST_AH + aRO[mt] + ((ka + xa) ^ aXR[mt]));
            // hh
#pragma unroll
            for (int mt = 0; mt < 4; mt++)
#pragma unroll
                for (int nt = 0; nt < 4; nt++)
                    mma16816(acc[mt][nt], aH[mt], &bH[nt >> 1][(nt & 1) << 1]);
#pragma unroll
            for (int mt = 0; mt < 4; mt++)
                ldsm4(aL[mt], sb + ST_AL + aRO[mt] + ((ka + xa) ^ aXR[mt]));
            // lh
#pragma unroll
            for (int mt = 0; mt < 4; mt++)
#pragma unroll
                for (int nt = 0; nt < 4; nt++)
                    mma16816(acc[mt][nt], aL[mt], &bH[nt >> 1][(nt & 1) << 1]);
#pragma unroll
            for (int p = 0; p < 2; p++)
                ldsm4(bL[p], sb + ST_BL + bRO[p] + ((ka + xb) ^ bXR[p]));
            // hl
#pragma unroll
            for (int mt = 0; mt < 4; mt++)
#pragma unroll
                for (int nt = 0; nt < 4; nt++)
                    mma16816(acc[mt][nt], aH[mt], &bL[nt >> 1][(nt & 1) << 1]);
        }

        sc++; if (sc == 3) sc = 0;
        si++; if (si == 3) si = 0;
    }

    float* Pz = bz ? g_P1 : g_P0;
    int erow = by * 128 + warp_m + (lane >> 2);
    int ecol = bx * 128 + warp_n + (lane & 3) * 2;
#pragma unroll
    for (int mt = 0; mt < 4; mt++) {
#pragma unroll
        for (int nt = 0; nt < 4; nt++) {
            int row = erow + mt * 16;
            int col = ecol + nt * 8;
            *(float2*)(Pz + (size_t)row * Dd + col) =
                make_float2(acc[mt][nt][0], acc[mt][nt][1]);
            *(float2*)(Pz + (size_t)(row + 8) * Dd + col) =
                make_float2(acc[mt][nt][2], acc[mt][nt][3]);
        }
    }
}

// ---------------- combine partials + bias + relu ----------------------------
__global__ void k_relu(const float* __restrict__ bias) {
    size_t e = ((size_t)blockIdx.x * 256 + threadIdx.x) * 4;
    int col = (int)(e & (Dd - 1));
    float4 a = *(const float4*)(g_P0 + e);
    float4 b = *(const float4*)(g_P1 + e);
    float4 bi = *(const float4*)(bias + col);
    float4 o;
    o.x = fmaxf(a.x + b.x + bi.x, 0.f);
    o.y = fmaxf(a.y + b.y + bi.y, 0.f);
    o.z = fmaxf(a.z + b.z + bi.z, 0.f);
    o.w = fmaxf(a.w + b.w + bi.w, 0.f);
    *(float4*)(g_X + e) = o;
}

// ---------------- heads: 16 rows / block, smem-tiled ------------------------
__global__ __launch_bounds__(256)
void k_heads2(const float* __restrict__ Wc, const float* __restrict__ bc,
              const float* __restrict__ Wb, const float* __restrict__ bb_,
              float* __restrict__ out) {
    __shared__ float Xs[16][64];
    __shared__ float Ws[64][106];
    __shared__ float ob[16][105];
    int r0 = blockIdx.x * 16, tid = threadIdx.x;
    float acc[7];
#pragma unroll
    for (int it = 0; it < 7; it++) acc[it] = 0.f;

    for (int kc = 0; kc < 64; kc++) {
        for (int q = tid; q < 16 * 64; q += 256) {
            int r = q >> 6, k = q & 63;
            Xs[r][k] = g_X[(size_t)(r0 + r) * Dd + kc * 64 + k];
        }
        for (int q = tid; q < 64 * 105; q += 256) {
            int k = q / 105, cc = q % 105;
            Ws[k][cc] = (cc < NC) ? Wc[(size_t)(kc * 64 + k) * NC + cc]
                                  : Wb[(size_t)(kc * 64 + k) * NBB + (cc - NC)];
        }
        __syncthreads();
#pragma unroll
        for (int it = 0; it < 7; it++) {
            int o = tid + it * 256;
            if (o < 16 * 105) {
                int r = o / 105, cc = o % 105;
                float a = acc[it];
#pragma unroll 8
                for (int k = 0; k < 64; k++) a += Xs[r][k] * Ws[k][cc];
                acc[it] = a;
            }
        }
        __syncthreads();
    }

#pragma unroll
    for (int it = 0; it < 7; it++) {
        int o = tid + it * 256;
        if (o < 16 * 105) {
            int r = o / 105, cc = o % 105;
            ob[r][cc] = acc[it] + ((cc < NC) ? bc[cc] : bb_[cc - NC]);
        }
    }
    __syncthreads();

    int w = tid >> 5, lane = tid & 31;
    for (int rr = w; rr < 16; rr += 8) {
        float v = (lane < NC) ? ob[rr][lane] : -3.4e38f;
        float m = v;
        for (int o = 16; o; o >>= 1) m = fmaxf(m, __shfl_xor_sync(0xffffffffu, m, o));
        float e = (lane < NC) ? expf(v - m) : 0.f;
        float s = e;
        for (int o = 16; o; o >>= 1) s += __shfl_xor_sync(0xffffffffu, s, o);
        if (lane < NC) out[(size_t)(r0 + rr) * NOUT + lane] = e / s;
    }
    for (int q = tid; q < 16 * NBB; q += 256) {
        int rr = q / NBB, cc = NC + q % NBB;
        out[(size_t)(r0 + rr) * NOUT + cc] = ob[rr][cc];
    }
}

// ---------------- host orchestration ----------------------------------------
extern "C" void kernel_launch(void* const* d_in, const int* in_sizes, int n_in,
                              void* d_out, int out_size) {
    const float* rois = (const float*)d_in[0];
    const float* P    = (const float*)d_in[1];
    const float* W1   = (const float*)d_in[2];
    const float* b1   = (const float*)d_in[3];
    const float* W2   = (const float*)d_in[4];
    const float* b2   = (const float*)d_in[5];
    const float* Wc   = (const float*)d_in[6];
    const float* bc   = (const float*)d_in[7];
    const float* Wb   = (const float*)d_in[8];
    const float* bb   = (const float*)d_in[9];
    float* out = (float*)d_out;

    void* xaddr = nullptr;
    cudaGetSymbolAddress(&xaddr, g_X);

    cudaFuncSetAttribute(k_gemm_mma, cudaFuncAttributeMaxDynamicSharedMemorySize,
                         GSMEM);

    k_keys<<<1, 1>>>();
    k_boxprep<<<(Nn + 255) / 256, 256>>>(rois);
    k_mask<<<Nn, 256>>>();
    k_sim<<<Nn, 256>>>(P);

    dim3 ggrid(Dd / 128, Nn / 128, 2);       // (32, 16, 2) split-K
    const int PREP_GRID = Nn + (Dd / 32) * (Dd / 64);  // 2048 + 8192
    const int RELU_GRID = (Nn * Dd) / (4 * 256);       // 8192

    // layer 1
    k_prep<<<PREP_GRID, 256>>>(P, W1);
    k_gemm_mma<<<ggrid, 256, GSMEM>>>();
    k_relu<<<RELU_GRID, 256>>>(b1);

    // layer 2
    k_prep<<<PREP_GRID, 256>>>((const float*)xaddr, W2);
    k_gemm_mma<<<ggrid, 256, GSMEM>>>();
    k_relu<<<RELU_GRID, 256>>>(b2);

    k_heads2<<<Nn / 16, 256>>>(Wc, bc, Wb, bb, out);
}